// round 10
// baseline (speedup 1.0000x reference)
#include <cuda_runtime.h>

// Problem constants (B=1 fixed)
#define D_   24
#define H_   96
#define W_   96
#define C_   32
#define HW_  (H_*W_)          // 9216
#define S_   (D_*HW_)         // 221184
#define TOT_ (C_*S_)          // 7077888
#define OC_  54               // offset conv output channels
#define OCP_ 56               // padded
#define G_   4
#define CPG_ (C_/G_)
#define NPG_ (CPG_*S_)
#define STAT_BLOCKS 64

typedef unsigned long long u64;

// packed f32x2 FMA: d.lo += a.lo*b.lo ; d.hi += a.hi*b.hi  (2x FP32 rate)
#define FFMA2(d, a, b) \
    asm("fma.rn.f32x2 %0, %1, %2, %0;" : "+l"(d) : "l"(a), "l"(b))
#define PACK2(d, x) \
    asm("mov.b64 %0, {%1, %1};" : "=l"(d) : "r"(__float_as_uint(x)))

static __device__ __forceinline__ float2 unpk(u64 v) {
    unsigned int lo, hi;
    asm("mov.b64 {%0, %1}, %2;" : "=r"(lo), "=r"(hi) : "l"(v));
    float2 r; r.x = __uint_as_float(lo); r.y = __uint_as_float(hi);
    return r;
}

// Scratch (device globals: allocation-free, graph-capture safe)
__device__ float g_h[TOT_];
__device__ float g_t[TOT_];
__device__ float g_offb[OC_*S_];
__device__ float g_part[G_*STAT_BLOCKS*2];
__device__ float g_ms[G_*2];
__device__ float g_cw[27*C_*OCP_];   // transposed conv weights [tap][c][oc56]
__device__ float g_dw[27*C_*C_];     // transposed deform weights [tap][c][oc32]

// ---------------------------------------------------------------------------
__global__ void prep_cw(const float* __restrict__ ow, float* __restrict__ cw) {
    int idx = blockIdx.x * 256 + threadIdx.x;        // 48384
    if (idx >= 27*C_*OCP_) return;
    int oc  = idx % OCP_;
    int c   = (idx / OCP_) % C_;
    int tap = idx / (OCP_*C_);
    cw[idx] = (oc < OC_) ? ow[(oc*C_ + c)*27 + tap] : 0.f;
}
__global__ void prep_dw(const float* __restrict__ dw, float* __restrict__ dwr) {
    int idx = blockIdx.x * 256 + threadIdx.x;        // 27648
    if (idx >= 27*C_*C_) return;
    int oc  = idx & 31;
    int c   = (idx >> 5) & 31;
    int tap = idx >> 10;
    dwr[idx] = dw[(oc*C_ + c)*27 + tap];
}

// ---------------------------------------------------------------------------
// GroupNorm (unchanged, known good)
// ---------------------------------------------------------------------------
__global__ void gn_stats(const float* __restrict__ in) {
    int g = blockIdx.y;
    const float4* p = (const float4*)(in + (size_t)g * NPG_);
    const int n4 = NPG_ / 4;
    float s = 0.f, q = 0.f;
    for (int i = blockIdx.x * blockDim.x + threadIdx.x; i < n4; i += STAT_BLOCKS * 256) {
        float4 v = p[i];
        s += v.x + v.y + v.z + v.w;
        q += v.x*v.x + v.y*v.y + v.z*v.z + v.w*v.w;
    }
    __shared__ float sh[512];
    int t = threadIdx.x;
    sh[t] = s; sh[256 + t] = q;
    __syncthreads();
    for (int o = 128; o > 0; o >>= 1) {
        if (t < o) { sh[t] += sh[t + o]; sh[256 + t] += sh[256 + t + o]; }
        __syncthreads();
    }
    if (t == 0) {
        g_part[(g*STAT_BLOCKS + blockIdx.x)*2 + 0] = sh[0];
        g_part[(g*STAT_BLOCKS + blockIdx.x)*2 + 1] = sh[256];
    }
}

__global__ void gn_fin() {
    int g = blockIdx.x, t = threadIdx.x;
    __shared__ float a[64], b[64];
    a[t] = g_part[(g*STAT_BLOCKS + t)*2 + 0];
    b[t] = g_part[(g*STAT_BLOCKS + t)*2 + 1];
    __syncthreads();
    for (int o = 32; o > 0; o >>= 1) {
        if (t < o) { a[t] += a[t + o]; b[t] += b[t + o]; }
        __syncthreads();
    }
    if (t == 0) {
        float mean = a[0] / (float)NPG_;
        float var  = b[0] / (float)NPG_ - mean * mean;
        g_ms[g*2 + 0] = mean;
        g_ms[g*2 + 1] = rsqrtf(var + 1e-5f);
    }
}

__global__ void gn_apply(const float* __restrict__ in, const float* __restrict__ gamma,
                         const float* __restrict__ beta, float* __restrict__ out) {
    int i4 = blockIdx.x * blockDim.x + threadIdx.x;
    int c  = i4 / (S_ / 4);
    int g  = c >> 3;
    float mean = g_ms[g*2 + 0], rstd = g_ms[g*2 + 1];
    float sc = rstd * gamma[c];
    float sb = beta[c] - mean * sc;
    float4 v = ((const float4*)in)[i4];
    float4 r;
    r.x = fmaxf(fmaf(v.x, sc, sb), 0.f);
    r.y = fmaxf(fmaf(v.y, sc, sb), 0.f);
    r.z = fmaxf(fmaf(v.z, sc, sb), 0.f);
    r.w = fmaxf(fmaf(v.w, sc, sb), 0.f);
    ((float4*)out)[i4] = r;
}

// ---------------------------------------------------------------------------
// Offset conv as register-blocked GEMM, 2 output rows per block, R6 staging.
// Block 224 = 32 vgroups x 7 oc-warps. Thread tile: 2 rows x 3 voxels x 8 ocs.
// Per (ti,tj): stage input rows zh,zh+1 (zero-filled OOB) + 3 taps' weights.
// Per c-step per warp: 10 LDS.32 + 6 LDS.128(bcast, shared by rows) + 72 FFMA2.
// Grid (D, H/2).
// ---------------------------------------------------------------------------
#define IN_PITCH 100
__global__ void __launch_bounds__(224)
conv_gemm(const float* __restrict__ in, const float* __restrict__ cw,
          const float* __restrict__ bias, float* __restrict__ out) {
    __shared__ __align__(16) float s_in[2 * C_ * IN_PITCH];   // 25.6 KB
    __shared__ __align__(16) float s_w[3 * C_ * OCP_];        // 21.5 KB

    int vg = threadIdx.x & 31;
    int og = threadIdx.x >> 5;
    int d  = blockIdx.x;
    int h0 = blockIdx.y * 2;        // output rows h0, h0+1

    u64 acc[24];                    // row0: v*4+p ; row1: 12+v*4+p
    #pragma unroll
    for (int i = 0; i < 24; i++) acc[i] = 0ull;

    #pragma unroll 1
    for (int ti = 0; ti < 3; ++ti) {
        int zd = d + ti - 1;
        if ((unsigned)zd >= D_) continue;             // uniform
        #pragma unroll 1
        for (int tj = 0; tj < 3; ++tj) {
            int zh = h0 + tj - 1;                     // rows zh (out h0), zh+1 (out h0+1)

            __syncthreads();
            // stage 2 input rows, zero-filled when OOB in h or w
            {
                const float* db = in + zd * HW_;
                for (int idx = threadIdx.x; idx < 2 * C_ * 98; idx += 224) {
                    int rr  = idx / (C_ * 98);        // 0/1
                    int rem = idx - rr * (C_ * 98);
                    int c   = rem / 98;
                    int t   = rem - c * 98;
                    int zhr = zh + rr;
                    int ww  = t - 1;
                    float v = 0.f;
                    if ((unsigned)zhr < H_ && (unsigned)ww < W_)
                        v = db[c * S_ + zhr * W_ + ww];
                    s_in[(rr * C_ + c) * IN_PITCH + t] = v;
                }
            }
            // stage 3 taps' weights (same as R6)
            {
                int tapb = (ti * 9 + tj * 3) * (C_ * OCP_);
                for (int idx = threadIdx.x; idx < 3 * C_ * OCP_; idx += 224)
                    s_w[idx] = cw[tapb + idx];
            }
            __syncthreads();

            #pragma unroll 2
            for (int c = 0; c < C_; ++c) {
                const float* sr0 = s_in + c * IN_PITCH + 3 * vg;
                const float* sr1 = s_in + (C_ + c) * IN_PITCH + 3 * vg;
                u64 pv0[5], pv1[5];
                #pragma unroll
                for (int t = 0; t < 5; ++t) { PACK2(pv0[t], sr0[t]); }
                #pragma unroll
                for (int t = 0; t < 5; ++t) { PACK2(pv1[t], sr1[t]); }
                #pragma unroll
                for (int tk = 0; tk < 3; ++tk) {
                    const ulonglong2* wq =
                        (const ulonglong2*)(s_w + (tk * C_ + c) * OCP_ + og * 8);
                    ulonglong2 w0 = wq[0];
                    ulonglong2 w1 = wq[1];
                    #pragma unroll
                    for (int v = 0; v < 3; ++v) {
                        u64 b0 = pv0[tk + v];
                        u64 b1 = pv1[tk + v];
                        FFMA2(acc[v*4 + 0],      w0.x, b0);
                        FFMA2(acc[v*4 + 1],      w0.y, b0);
                        FFMA2(acc[v*4 + 2],      w1.x, b0);
                        FFMA2(acc[v*4 + 3],      w1.y, b0);
                        FFMA2(acc[12 + v*4 + 0], w0.x, b1);
                        FFMA2(acc[12 + v*4 + 1], w0.y, b1);
                        FFMA2(acc[12 + v*4 + 2], w1.x, b1);
                        FFMA2(acc[12 + v*4 + 3], w1.y, b1);
                    }
                }
            }
        }
    }

    int sprow = (d * H_ + h0) * W_ + 3 * vg;
    #pragma unroll
    for (int p = 0; p < 4; ++p) {
        int oc = og * 8 + 2 * p;
        if (oc < OC_) {
            float bx = __ldg(bias + oc);
            float by = __ldg(bias + oc + 1);
            #pragma unroll
            for (int v = 0; v < 3; ++v) {
                float2 a0 = unpk(acc[v*4 + p]);
                float2 a1 = unpk(acc[12 + v*4 + p]);
                out[(oc+0) * S_ + sprow + v]      = a0.x + bx;
                out[(oc+1) * S_ + sprow + v]      = a0.y + by;
                out[(oc+0) * S_ + sprow + W_ + v] = a1.x + bx;
                out[(oc+1) * S_ + sprow + W_ + v] = a1.y + by;
            }
        }
    }
}

// ---------------------------------------------------------------------------
// Deformable conv (Round 9 version verbatim — known good).
// ---------------------------------------------------------------------------
__global__ void __launch_bounds__(256)
deform(const float* __restrict__ in, const float* __restrict__ offs,
       const float* __restrict__ dwt, const float* __restrict__ bias,
       const float* __restrict__ resid, float* __restrict__ out) {
    __shared__ __align__(16) float ws[9 * C_ * C_];   // 36 KB
    int sp = blockIdx.x * 256 + threadIdx.x;
    int d = sp / HW_;
    int r = sp - d * HW_;
    int h = r / W_;
    int w = r - h * W_;

    u64 acc[16];
    #pragma unroll
    for (int i = 0; i < 16; i++) acc[i] = 0ull;

    #pragma unroll 1
    for (int ti = 0; ti < 3; ++ti) {
        __syncthreads();
        {
            const float4* src = (const float4*)(dwt + ti * (9 * C_ * C_));
            float4* dst = (float4*)ws;
            for (int idx = threadIdx.x; idx < 9 * C_ * C_ / 4; idx += 256)
                dst[idx] = src[idx];
        }
        __syncthreads();
        int zd = d + ti - 1;
        if ((unsigned)zd >= D_) continue;
        const float* base = in + zd * HW_;

        #pragma unroll 1
        for (int tl = 0; tl < 9; ++tl) {
            int tj = tl / 3, tk = tl - 3 * tj;
            int tap = ti * 9 + tl;

            float offh = offs[(2*tap + 0) * S_ + sp];
            float offw = offs[(2*tap + 1) * S_ + sp];
            float hp = (float)(h + tj - 1) + offh;
            float wp = (float)(w + tk - 1) + offw;
            float h0f = floorf(hp), w0f = floorf(wp);
            int h0 = (int)h0f, w0 = (int)w0f;
            float lh = hp - h0f, lw = wp - w0f;

            float m00 = ((unsigned)h0     < H_ && (unsigned)w0     < W_) ? 1.f : 0.f;
            float m01 = ((unsigned)h0     < H_ && (unsigned)(w0+1) < W_) ? 1.f : 0.f;
            float m10 = ((unsigned)(h0+1) < H_ && (unsigned)w0     < W_) ? 1.f : 0.f;
            float m11 = ((unsigned)(h0+1) < H_ && (unsigned)(w0+1) < W_) ? 1.f : 0.f;
            float w00 = (1.f - lh) * (1.f - lw) * m00;
            float w01 = (1.f - lh) * lw         * m01;
            float w10 = lh         * (1.f - lw) * m10;
            float w11 = lh         * lw         * m11;

            int h0c = min(max(h0,     0), H_ - 1);
            int h1c = min(max(h0 + 1, 0), H_ - 1);
            int w0c = min(max(w0,     0), W_ - 1);
            int w1c = min(max(w0 + 1, 0), W_ - 1);
            int i00 = h0c * W_ + w0c;
            int i01 = h0c * W_ + w1c;
            int i10 = h1c * W_ + w0c;
            int i11 = h1c * W_ + w1c;

            const float* wp_s = ws + tl * (C_ * C_);
            #pragma unroll 4
            for (int c = 0; c < C_; c++) {
                const float* pc = base + c * S_;
                float val = w00 * __ldg(pc + i00) + w01 * __ldg(pc + i01)
                          + w10 * __ldg(pc + i10) + w11 * __ldg(pc + i11);
                u64 bv; PACK2(bv, val);
                const ulonglong2* wq = (const ulonglong2*)(wp_s + c * C_);
                #pragma unroll
                for (int q = 0; q < 8; q++) {
                    ulonglong2 t = wq[q];
                    FFMA2(acc[2*q + 0], t.x, bv);
                    FFMA2(acc[2*q + 1], t.y, bv);
                }
            }
        }
    }

    if (resid) {
        #pragma unroll
        for (int q = 0; q < 16; ++q) {
            int oc = 2 * q;
            float2 a = unpk(acc[q]);
            int i0 = (oc+0) * S_ + sp, i1 = (oc+1) * S_ + sp;
            out[i0] = a.x + __ldg(bias + oc)     + __ldg(resid + i0);
            out[i1] = a.y + __ldg(bias + oc + 1) + __ldg(resid + i1);
        }
    } else {
        #pragma unroll
        for (int q = 0; q < 16; ++q) {
            int oc = 2 * q;
            float2 a = unpk(acc[q]);
            out[(oc+0) * S_ + sp] = a.x + __ldg(bias + oc);
            out[(oc+1) * S_ + sp] = a.y + __ldg(bias + oc + 1);
        }
    }
}

// ---------------------------------------------------------------------------
extern "C" void kernel_launch(void* const* d_in, const int* in_sizes, int n_in,
                              void* d_out, int out_size) {
    const float* x   = (const float*)d_in[0];
    const float* g1  = (const float*)d_in[1];
    const float* be1 = (const float*)d_in[2];
    const float* g2  = (const float*)d_in[3];
    const float* be2 = (const float*)d_in[4];
    const float* ow1 = (const float*)d_in[5];
    const float* ob1 = (const float*)d_in[6];
    const float* dw1 = (const float*)d_in[7];
    const float* db1 = (const float*)d_in[8];
    const float* ow2 = (const float*)d_in[9];
    const float* ob2 = (const float*)d_in[10];
    const float* dw2 = (const float*)d_in[11];
    const float* db2 = (const float*)d_in[12];
    float* out = (float*)d_out;

    float *ph, *pt, *poff, *pcw, *pdw;
    cudaGetSymbolAddress((void**)&ph,   g_h);
    cudaGetSymbolAddress((void**)&pt,   g_t);
    cudaGetSymbolAddress((void**)&poff, g_offb);
    cudaGetSymbolAddress((void**)&pcw,  g_cw);
    cudaGetSymbolAddress((void**)&pdw,  g_dw);

    dim3 sg(STAT_BLOCKS, G_);
    const int NB_GN = TOT_ / 4 / 256;
    const int NB_SP = S_ / 256;
    dim3 gc(D_, H_/2);

    // pass 1
    prep_cw<<<(27*C_*OCP_ + 255)/256, 256>>>(ow1, pcw);
    prep_dw<<<(27*C_*C_  + 255)/256, 256>>>(dw1, pdw);
    gn_stats<<<sg, 256>>>(x);
    gn_fin<<<G_, 64>>>();
    gn_apply<<<NB_GN, 256>>>(x, g1, be1, ph);
    conv_gemm<<<gc, 224>>>(ph, pcw, ob1, poff);
    deform<<<NB_SP, 256>>>(ph, poff, pdw, db1, nullptr, pt);

    // pass 2 (+ residual into d_out)
    prep_cw<<<(27*C_*OCP_ + 255)/256, 256>>>(ow2, pcw);
    prep_dw<<<(27*C_*C_  + 255)/256, 256>>>(dw2, pdw);
    gn_stats<<<sg, 256>>>(pt);
    gn_fin<<<G_, 64>>>();
    gn_apply<<<NB_GN, 256>>>(pt, g2, be2, ph);
    conv_gemm<<<gc, 224>>>(ph, pcw, ob2, poff);
    deform<<<NB_SP, 256>>>(ph, poff, pdw, db2, x, out);
}

// round 11
// speedup vs baseline: 1.1085x; 1.1085x over previous
#include <cuda_runtime.h>

// Problem constants (B=1 fixed)
#define D_   24
#define H_   96
#define W_   96
#define C_   32
#define HW_  (H_*W_)          // 9216
#define S_   (D_*HW_)         // 221184
#define TOT_ (C_*S_)          // 7077888
#define OC_  54               // offset conv output channels
#define OCP_ 56               // padded
#define G_   4
#define CPG_ (C_/G_)
#define NPG_ (CPG_*S_)
#define STAT_BLOCKS 64

typedef unsigned long long u64;

// packed f32x2 FMA: d.lo += a.lo*b.lo ; d.hi += a.hi*b.hi  (2x FP32 rate)
#define FFMA2(d, a, b) \
    asm("fma.rn.f32x2 %0, %1, %2, %0;" : "+l"(d) : "l"(a), "l"(b))
#define PACK2(d, x) \
    asm("mov.b64 %0, {%1, %1};" : "=l"(d) : "r"(__float_as_uint(x)))

#define CP_ASYNC16(dst_u32, src_ptr) \
    asm volatile("cp.async.cg.shared.global [%0], [%1], 16;" :: "r"(dst_u32), "l"(src_ptr))
#define CP_COMMIT() asm volatile("cp.async.commit_group;")
#define CP_WAIT1()  asm volatile("cp.async.wait_group 1;")

static __device__ __forceinline__ float2 unpk(u64 v) {
    unsigned int lo, hi;
    asm("mov.b64 {%0, %1}, %2;" : "=r"(lo), "=r"(hi) : "l"(v));
    float2 r; r.x = __uint_as_float(lo); r.y = __uint_as_float(hi);
    return r;
}
static __device__ __forceinline__ unsigned int smem_u32(const void* p) {
    unsigned int a;
    asm("{ .reg .u64 t; cvta.to.shared.u64 t, %1; cvt.u32.u64 %0, t; }" : "=r"(a) : "l"(p));
    return a;
}

// Scratch (device globals: allocation-free, graph-capture safe)
__device__ float g_h[TOT_];
__device__ float g_t[TOT_];
__device__ float g_offb[OC_*S_];
__device__ float g_part[G_*STAT_BLOCKS*2];
__device__ float g_ms[G_*2];
__device__ float g_cw[27*C_*OCP_];   // transposed conv weights [tap][c][oc56]
__device__ float g_dw[27*C_*C_];     // transposed deform weights [tap][c][oc32]

// ---------------------------------------------------------------------------
__global__ void prep_cw(const float* __restrict__ ow, float* __restrict__ cw) {
    int idx = blockIdx.x * 256 + threadIdx.x;        // 48384
    if (idx >= 27*C_*OCP_) return;
    int oc  = idx % OCP_;
    int c   = (idx / OCP_) % C_;
    int tap = idx / (OCP_*C_);
    cw[idx] = (oc < OC_) ? ow[(oc*C_ + c)*27 + tap] : 0.f;
}
__global__ void prep_dw(const float* __restrict__ dw, float* __restrict__ dwr) {
    int idx = blockIdx.x * 256 + threadIdx.x;        // 27648
    if (idx >= 27*C_*C_) return;
    int oc  = idx & 31;
    int c   = (idx >> 5) & 31;
    int tap = idx >> 10;
    dwr[idx] = dw[(oc*C_ + c)*27 + tap];
}

// ---------------------------------------------------------------------------
// GroupNorm (unchanged, known good)
// ---------------------------------------------------------------------------
__global__ void gn_stats(const float* __restrict__ in) {
    int g = blockIdx.y;
    const float4* p = (const float4*)(in + (size_t)g * NPG_);
    const int n4 = NPG_ / 4;
    float s = 0.f, q = 0.f;
    for (int i = blockIdx.x * blockDim.x + threadIdx.x; i < n4; i += STAT_BLOCKS * 256) {
        float4 v = p[i];
        s += v.x + v.y + v.z + v.w;
        q += v.x*v.x + v.y*v.y + v.z*v.z + v.w*v.w;
    }
    __shared__ float sh[512];
    int t = threadIdx.x;
    sh[t] = s; sh[256 + t] = q;
    __syncthreads();
    for (int o = 128; o > 0; o >>= 1) {
        if (t < o) { sh[t] += sh[t + o]; sh[256 + t] += sh[256 + t + o]; }
        __syncthreads();
    }
    if (t == 0) {
        g_part[(g*STAT_BLOCKS + blockIdx.x)*2 + 0] = sh[0];
        g_part[(g*STAT_BLOCKS + blockIdx.x)*2 + 1] = sh[256];
    }
}

__global__ void gn_fin() {
    int g = blockIdx.x, t = threadIdx.x;
    __shared__ float a[64], b[64];
    a[t] = g_part[(g*STAT_BLOCKS + t)*2 + 0];
    b[t] = g_part[(g*STAT_BLOCKS + t)*2 + 1];
    __syncthreads();
    for (int o = 32; o > 0; o >>= 1) {
        if (t < o) { a[t] += a[t + o]; b[t] += b[t + o]; }
        __syncthreads();
    }
    if (t == 0) {
        float mean = a[0] / (float)NPG_;
        float var  = b[0] / (float)NPG_ - mean * mean;
        g_ms[g*2 + 0] = mean;
        g_ms[g*2 + 1] = rsqrtf(var + 1e-5f);
    }
}

__global__ void gn_apply(const float* __restrict__ in, const float* __restrict__ gamma,
                         const float* __restrict__ beta, float* __restrict__ out) {
    int i4 = blockIdx.x * blockDim.x + threadIdx.x;
    int c  = i4 / (S_ / 4);
    int g  = c >> 3;
    float mean = g_ms[g*2 + 0], rstd = g_ms[g*2 + 1];
    float sc = rstd * gamma[c];
    float sb = beta[c] - mean * sc;
    float4 v = ((const float4*)in)[i4];
    float4 r;
    r.x = fmaxf(fmaf(v.x, sc, sb), 0.f);
    r.y = fmaxf(fmaf(v.y, sc, sb), 0.f);
    r.z = fmaxf(fmaf(v.z, sc, sb), 0.f);
    r.w = fmaxf(fmaf(v.w, sc, sb), 0.f);
    ((float4*)out)[i4] = r;
}

// ---------------------------------------------------------------------------
// Offset conv, R6 tile shape + cp.async DOUBLE-BUFFERED staging.
// Block 224 = 32 vgroups x 7 oc-warps; thread tile 3 voxels x 8 ocs.
// Dynamic smem: s_in[2][32][104] + s_w[2][3*32*56] = 68 KB.
// Input layout: w=0..95 at slots 4..99 (16B-aligned for cp.async),
// halo slots 3 (w=-1) and 100 (w=96) pre-zeroed once.
// Phase p=(ti*3+tj); prefetch p+1 during compute of p; wait_group<1> ring.
// Grid (D, H).
// ---------------------------------------------------------------------------
#define INP_ 104
#define SMEM_CONV ((2*C_*INP_ + 2*3*C_*OCP_) * 4)    // 69632 bytes
__global__ void __launch_bounds__(224)
conv_gemm(const float* __restrict__ in, const float* __restrict__ cw,
          const float* __restrict__ bias, float* __restrict__ out) {
    extern __shared__ __align__(16) float smem[];
    float* s_in = smem;                         // 2 x C_ x INP_
    float* s_w  = smem + 2 * C_ * INP_;         // 2 x 3*C_*OCP_
    unsigned int sin_a = smem_u32(s_in);
    unsigned int sw_a  = smem_u32(s_w);

    int vg = threadIdx.x & 31;
    int og = threadIdx.x >> 5;
    int d  = blockIdx.x;
    int h  = blockIdx.y;

    // zero the two halo columns of both input buffers (never written by cp.async)
    for (int i = threadIdx.x; i < 2 * C_; i += 224) {
        s_in[i * INP_ + 3]   = 0.f;
        s_in[i * INP_ + 100] = 0.f;
    }

    u64 acc[12];
    #pragma unroll
    for (int i = 0; i < 12; i++) acc[i] = 0ull;

    // ---- prefetch phase 0 ----
    {
        int zd = d - 1, zh = h - 1;
        if ((unsigned)zd < D_ && (unsigned)zh < H_) {
            const float* rb = in + zd * HW_ + zh * W_;
            for (int idx = threadIdx.x; idx < C_ * 24; idx += 224) {
                int c = idx / 24, q = idx - c * 24;
                CP_ASYNC16(sin_a + (c * INP_ + 4 + 4*q) * 4, rb + c * S_ + 4*q);
            }
            const float* wb = cw;               // taps 0..2
            for (int idx = threadIdx.x; idx < (3*C_*OCP_)/4; idx += 224)
                CP_ASYNC16(sw_a + idx * 16, wb + 4*idx);
        }
    }
    CP_COMMIT();

    #pragma unroll 1
    for (int p = 0; p < 9; ++p) {
        // prefetch phase p+1 into buffer (p+1)&1
        if (p < 8) {
            int pn = p + 1;
            int ti = pn / 3, tj = pn - 3 * ti;
            int zd = d + ti - 1, zh = h + tj - 1;
            if ((unsigned)zd < D_ && (unsigned)zh < H_) {
                int b = pn & 1;
                const float* rb = in + zd * HW_ + zh * W_;
                unsigned int din = sin_a + (b * C_ * INP_) * 4;
                for (int idx = threadIdx.x; idx < C_ * 24; idx += 224) {
                    int c = idx / 24, q = idx - c * 24;
                    CP_ASYNC16(din + (c * INP_ + 4 + 4*q) * 4, rb + c * S_ + 4*q);
                }
                const float* wb = cw + pn * 3 * (C_ * OCP_);
                unsigned int dw = sw_a + (b * 3 * C_ * OCP_) * 4;
                for (int idx = threadIdx.x; idx < (3*C_*OCP_)/4; idx += 224)
                    CP_ASYNC16(dw + idx * 16, wb + 4*idx);
            }
        }
        CP_COMMIT();            // empty group when p==8
        CP_WAIT1();             // phase p's group retired (in-order)
        __syncthreads();

        int ti = p / 3, tj = p - 3 * ti;
        int zd = d + ti - 1, zh = h + tj - 1;
        if ((unsigned)zd < D_ && (unsigned)zh < H_) {
            const float* bin = s_in + (p & 1) * C_ * INP_;
            const float* bw  = s_w  + (p & 1) * 3 * C_ * OCP_;

            #pragma unroll 2
            for (int c = 0; c < C_; ++c) {
                const float* sr = bin + c * INP_ + 3 * vg + 3;
                u64 pv[5];
                #pragma unroll
                for (int t = 0; t < 5; ++t) { PACK2(pv[t], sr[t]); }
                #pragma unroll
                for (int tk = 0; tk < 3; ++tk) {
                    const ulonglong2* wq =
                        (const ulonglong2*)(bw + (tk * C_ + c) * OCP_ + og * 8);
                    ulonglong2 w0 = wq[0];
                    ulonglong2 w1 = wq[1];
                    #pragma unroll
                    for (int v = 0; v < 3; ++v) {
                        u64 b = pv[tk + v];
                        FFMA2(acc[v*4 + 0], w0.x, b);
                        FFMA2(acc[v*4 + 1], w0.y, b);
                        FFMA2(acc[v*4 + 2], w1.x, b);
                        FFMA2(acc[v*4 + 3], w1.y, b);
                    }
                }
            }
        }
        __syncthreads();        // protect buffer p before p+2 prefetch overwrites
    }

    int sprow = (d * H_ + h) * W_ + 3 * vg;
    #pragma unroll
    for (int p = 0; p < 4; ++p) {
        int oc = og * 8 + 2 * p;
        if (oc < OC_) {
            float bx = __ldg(bias + oc);
            float by = __ldg(bias + oc + 1);
            #pragma unroll
            for (int v = 0; v < 3; ++v) {
                float2 a = unpk(acc[v*4 + p]);
                out[(oc+0) * S_ + sprow + v] = a.x + bx;
                out[(oc+1) * S_ + sprow + v] = a.y + by;
            }
        }
    }
}

// ---------------------------------------------------------------------------
// Deformable conv (Round 9 version verbatim — known good).
// ---------------------------------------------------------------------------
__global__ void __launch_bounds__(256)
deform(const float* __restrict__ in, const float* __restrict__ offs,
       const float* __restrict__ dwt, const float* __restrict__ bias,
       const float* __restrict__ resid, float* __restrict__ out) {
    __shared__ __align__(16) float ws[9 * C_ * C_];   // 36 KB
    int sp = blockIdx.x * 256 + threadIdx.x;
    int d = sp / HW_;
    int r = sp - d * HW_;
    int h = r / W_;
    int w = r - h * W_;

    u64 acc[16];
    #pragma unroll
    for (int i = 0; i < 16; i++) acc[i] = 0ull;

    #pragma unroll 1
    for (int ti = 0; ti < 3; ++ti) {
        __syncthreads();
        {
            const float4* src = (const float4*)(dwt + ti * (9 * C_ * C_));
            float4* dst = (float4*)ws;
            for (int idx = threadIdx.x; idx < 9 * C_ * C_ / 4; idx += 256)
                dst[idx] = src[idx];
        }
        __syncthreads();
        int zd = d + ti - 1;
        if ((unsigned)zd >= D_) continue;
        const float* base = in + zd * HW_;

        #pragma unroll 1
        for (int tl = 0; tl < 9; ++tl) {
            int tj = tl / 3, tk = tl - 3 * tj;
            int tap = ti * 9 + tl;

            float offh = offs[(2*tap + 0) * S_ + sp];
            float offw = offs[(2*tap + 1) * S_ + sp];
            float hp = (float)(h + tj - 1) + offh;
            float wp = (float)(w + tk - 1) + offw;
            float h0f = floorf(hp), w0f = floorf(wp);
            int h0 = (int)h0f, w0 = (int)w0f;
            float lh = hp - h0f, lw = wp - w0f;

            float m00 = ((unsigned)h0     < H_ && (unsigned)w0     < W_) ? 1.f : 0.f;
            float m01 = ((unsigned)h0     < H_ && (unsigned)(w0+1) < W_) ? 1.f : 0.f;
            float m10 = ((unsigned)(h0+1) < H_ && (unsigned)w0     < W_) ? 1.f : 0.f;
            float m11 = ((unsigned)(h0+1) < H_ && (unsigned)(w0+1) < W_) ? 1.f : 0.f;
            float w00 = (1.f - lh) * (1.f - lw) * m00;
            float w01 = (1.f - lh) * lw         * m01;
            float w10 = lh         * (1.f - lw) * m10;
            float w11 = lh         * lw         * m11;

            int h0c = min(max(h0,     0), H_ - 1);
            int h1c = min(max(h0 + 1, 0), H_ - 1);
            int w0c = min(max(w0,     0), W_ - 1);
            int w1c = min(max(w0 + 1, 0), W_ - 1);
            int i00 = h0c * W_ + w0c;
            int i01 = h0c * W_ + w1c;
            int i10 = h1c * W_ + w0c;
            int i11 = h1c * W_ + w1c;

            const float* wp_s = ws + tl * (C_ * C_);
            #pragma unroll 4
            for (int c = 0; c < C_; c++) {
                const float* pc = base + c * S_;
                float val = w00 * __ldg(pc + i00) + w01 * __ldg(pc + i01)
                          + w10 * __ldg(pc + i10) + w11 * __ldg(pc + i11);
                u64 bv; PACK2(bv, val);
                const ulonglong2* wq = (const ulonglong2*)(wp_s + c * C_);
                #pragma unroll
                for (int q = 0; q < 8; q++) {
                    ulonglong2 t = wq[q];
                    FFMA2(acc[2*q + 0], t.x, bv);
                    FFMA2(acc[2*q + 1], t.y, bv);
                }
            }
        }
    }

    if (resid) {
        #pragma unroll
        for (int q = 0; q < 16; ++q) {
            int oc = 2 * q;
            float2 a = unpk(acc[q]);
            int i0 = (oc+0) * S_ + sp, i1 = (oc+1) * S_ + sp;
            out[i0] = a.x + __ldg(bias + oc)     + __ldg(resid + i0);
            out[i1] = a.y + __ldg(bias + oc + 1) + __ldg(resid + i1);
        }
    } else {
        #pragma unroll
        for (int q = 0; q < 16; ++q) {
            int oc = 2 * q;
            float2 a = unpk(acc[q]);
            out[(oc+0) * S_ + sp] = a.x + __ldg(bias + oc);
            out[(oc+1) * S_ + sp] = a.y + __ldg(bias + oc + 1);
        }
    }
}

// ---------------------------------------------------------------------------
extern "C" void kernel_launch(void* const* d_in, const int* in_sizes, int n_in,
                              void* d_out, int out_size) {
    const float* x   = (const float*)d_in[0];
    const float* g1  = (const float*)d_in[1];
    const float* be1 = (const float*)d_in[2];
    const float* g2  = (const float*)d_in[3];
    const float* be2 = (const float*)d_in[4];
    const float* ow1 = (const float*)d_in[5];
    const float* ob1 = (const float*)d_in[6];
    const float* dw1 = (const float*)d_in[7];
    const float* db1 = (const float*)d_in[8];
    const float* ow2 = (const float*)d_in[9];
    const float* ob2 = (const float*)d_in[10];
    const float* dw2 = (const float*)d_in[11];
    const float* db2 = (const float*)d_in[12];
    float* out = (float*)d_out;

    float *ph, *pt, *poff, *pcw, *pdw;
    cudaGetSymbolAddress((void**)&ph,   g_h);
    cudaGetSymbolAddress((void**)&pt,   g_t);
    cudaGetSymbolAddress((void**)&poff, g_offb);
    cudaGetSymbolAddress((void**)&pcw,  g_cw);
    cudaGetSymbolAddress((void**)&pdw,  g_dw);

    cudaFuncSetAttribute(conv_gemm,
        cudaFuncAttributeMaxDynamicSharedMemorySize, SMEM_CONV);

    dim3 sg(STAT_BLOCKS, G_);
    const int NB_GN = TOT_ / 4 / 256;
    const int NB_SP = S_ / 256;
    dim3 gc(D_, H_);

    // pass 1
    prep_cw<<<(27*C_*OCP_ + 255)/256, 256>>>(ow1, pcw);
    prep_dw<<<(27*C_*C_  + 255)/256, 256>>>(dw1, pdw);
    gn_stats<<<sg, 256>>>(x);
    gn_fin<<<G_, 64>>>();
    gn_apply<<<NB_GN, 256>>>(x, g1, be1, ph);
    conv_gemm<<<gc, 224, SMEM_CONV>>>(ph, pcw, ob1, poff);
    deform<<<NB_SP, 256>>>(ph, poff, pdw, db1, nullptr, pt);

    // pass 2 (+ residual into d_out)
    prep_cw<<<(27*C_*OCP_ + 255)/256, 256>>>(ow2, pcw);
    prep_dw<<<(27*C_*C_  + 255)/256, 256>>>(dw2, pdw);
    gn_stats<<<sg, 256>>>(pt);
    gn_fin<<<G_, 64>>>();
    gn_apply<<<NB_GN, 256>>>(pt, g2, be2, ph);
    conv_gemm<<<gc, 224, SMEM_CONV>>>(ph, pcw, ob2, poff);
    deform<<<NB_SP, 256>>>(ph, poff, pdw, db2, x, out);
}